// round 2
// baseline (speedup 1.0000x reference)
#include <cuda_runtime.h>
#include <math.h>

#define DAYS  365
#define NY    30
#define SGRID 4000
#define TT    (DAYS * NY)
#define NPAIR 435
#define NQ    5
#define K1_SER 16

#define POSINF __int_as_float(0x7f800000)
#define FULLM  0xffffffffu

// ---------------- intermediate storage (no allocations allowed) -------------
__device__ float  g_pM[SGRID * NY];
__device__ float  g_tM[SGRID * NY];
__device__ float  g_pQ[SGRID * NQ * NY];
__device__ float  g_tQ[SGRID * NQ * NY];
__device__ double g_sse;
__device__ double g_trend;

// ---------------- warp bitonic sort of 512, LANE-MAJOR layout ---------------
// element index g = (lane<<4) | r. Ascending. Only 15 cross-lane stages
// (240 SHFLs) vs 35 (560 SHFLs) for the reg-major layout.
__device__ __forceinline__ void bsort512(float v[16], int lane) {
#pragma unroll
    for (int m = 2; m <= 512; m <<= 1) {
#pragma unroll
        for (int j = m >> 1; j >= 1; j >>= 1) {
            if (j >= 16) {
                // cross-lane: partner lane = lane ^ (j>>4), same register.
                // m >= 32 here, so direction depends only on lane.
                int  jl      = j >> 4;
                bool up      = ((lane & (m >> 4)) == 0);
                bool lower   = ((lane & jl) == 0);
                bool keepmin = (up == lower);
#pragma unroll
                for (int r = 0; r < 16; r++) {
                    float o = __shfl_xor_sync(FULLM, v[r], jl);
                    v[r] = keepmin ? fminf(v[r], o) : fmaxf(v[r], o);
                }
            } else {
                // register-register stage
#pragma unroll
                for (int r = 0; r < 16; r++) {
                    if ((r & j) == 0) {
                        int  r2 = r | j;
                        bool up = (m >= 16) ? ((lane & (m >> 4)) == 0)
                                            : ((r & m) == 0);
                        float a = v[r], b = v[r2];
                        float lo = fminf(a, b), hi = fmaxf(a, b);
                        v[r]  = up ? lo : hi;
                        v[r2] = up ? hi : lo;
                    }
                }
            }
        }
    }
}

// ---------------- kernel 0: zero accumulators --------------------------------
__global__ void k_zero() {
    g_sse = 0.0;
    g_trend = 0.0;
}

// ---------------- kernel 1: transpose + SSE + per-(series,year) sort ---------
// grid (SGRID/K1_SER, NY), block 512 (16 warps, 1 warp per series)
__global__ __launch_bounds__(512) void k_sortdays(const float* __restrict__ pred,
                                                  const float* __restrict__ obs) {
    __shared__ float shP[K1_SER][DAYS];
    __shared__ float shT[K1_SER][DAYS];
    __shared__ float warpsum[16];

    int y      = blockIdx.y;
    int s_base = blockIdx.x * K1_SER;
    int tid    = threadIdx.x;
    int w      = tid >> 5;
    int lane   = tid & 31;

    const float* pbase = pred + y * DAYS * SGRID + s_base;
    const float* tbase = obs  + y * DAYS * SGRID + s_base;

    // coalesced load + transpose + fused SSE
    float sse = 0.0f;
    for (int idx = tid; idx < DAYS * K1_SER; idx += 512) {
        int d  = idx >> 4;
        int sl = idx & 15;
        float a = pbase[d * SGRID + sl];
        float b = tbase[d * SGRID + sl];
        shP[sl][d] = a;
        shT[sl][d] = b;
        float df = a - b;
        sse += df * df;
    }
#pragma unroll
    for (int o = 16; o > 0; o >>= 1) sse += __shfl_down_sync(FULLM, sse, o);
    if (lane == 0) warpsum[w] = sse;
    __syncthreads();
    if (tid == 0) {
        float tot = 0.0f;
#pragma unroll
        for (int i = 0; i < 16; i++) tot += warpsum[i];
        atomicAdd(&g_sse, (double)tot);
    }

    int s = s_base + w;

#pragma unroll 1
    for (int pass = 0; pass < 2; pass++) {
        float (*sh)[DAYS] = pass ? shT : shP;
        float* outM = pass ? g_tM : g_pM;
        float* outQ = pass ? g_tQ : g_pQ;

        // Conflict-free smem read (consecutive lanes -> consecutive addrs).
        // The sort is order-insensitive, so this arbitrary value->slot
        // assignment is valid for the lane-major network.
        float v[16];
        float msum = 0.0f;
#pragma unroll
        for (int r = 0; r < 16; r++) {
            int g = (r << 5) | lane;
            if (g < DAYS) { v[r] = sh[w][g]; msum += v[r]; }
            else          { v[r] = POSINF; }
        }
        // yearly mean
#pragma unroll
        for (int o = 16; o > 0; o >>= 1) msum += __shfl_down_sync(FULLM, msum, o);
        if (lane == 0) outM[s * NY + y] = msum / (float)DAYS;

        bsort512(v, lane);

        // order statistics (lane-major): rank g -> lane g>>4, reg g&15
        if (lane == 22) {
            outQ[(s * NQ + 0) * NY + y] = v[12];  // g=364
            outQ[(s * NQ + 1) * NY + y] = v[5];   // g=357
        }
        if (lane == 11) outQ[(s * NQ + 2) * NY + y] = v[6];   // g=182
        if (lane == 6)  outQ[(s * NQ + 3) * NY + y] = v[13];  // g=109
        if (lane == 0)  outQ[(s * NQ + 4) * NY + y] = v[7];   // g=7
    }
}

// ---------------- kernel 2: Theil-Sen medians + trend terms ------------------
// grid SGRID, block 192 (6 warps: warp0 = mean, warps 1..5 = quantiles)
__global__ __launch_bounds__(192) void k_theil() {
    __shared__ float xs[6][2][NY];

    int s    = blockIdx.x;
    int w    = threadIdx.x >> 5;
    int lane = threadIdx.x & 31;

    const float* xp;
    const float* xt;
    if (w == 0) { xp = g_pM + s * NY;                  xt = g_tM + s * NY; }
    else        { xp = g_pQ + (s * NQ + (w - 1)) * NY; xt = g_tQ + (s * NQ + (w - 1)) * NY; }
    if (lane < NY) {
        xs[w][0][lane] = xp[lane];
        xs[w][1][lane] = xt[lane];
    }
    __syncwarp();

    // decode each slot's pair once, build both slope sets
    float vP[16], vT[16];
#pragma unroll
    for (int r = 0; r < 16; r++) {
        int p = (r << 5) | lane;   // arbitrary pair->slot assignment (median is order-insensitive)
        if (p < NPAIR) {
            int i = 0, rem = p, cnt = NY - 1;
            while (rem >= cnt) { rem -= cnt; i++; cnt--; }
            int j = i + 1 + rem;
            float denom = (float)(j - i);
            vP[r] = (xs[w][0][j] - xs[w][0][i]) / denom;
            vT[r] = (xs[w][1][j] - xs[w][1][i]) / denom;
        } else {
            vP[r] = POSINF;
            vT[r] = POSINF;
        }
    }

    bsort512(vP, lane);
    bsort512(vT, lane);

    // median of 435 = sorted element 217 -> lane 13, reg 9 (lane-major)
    float sp = __shfl_sync(FULLM, vP[9], 13);
    float st = __shfl_sync(FULLM, vT[9], 13);

    if (lane == 0) {
        double term;
        if (w == 0) { float d = st - sp;   term = (double)d * (double)d; }
        else        { float q = st / (-sp); term = (double)q * (double)q; }
        atomicAdd(&g_trend, term);
    }
}

// ---------------- kernel 3: finalize -----------------------------------------
__global__ void k_final(float* out) {
    double mse = g_sse / ((double)TT * (double)SGRID);
    out[0] = (float)(sqrt(mse) + g_trend / (double)SGRID);
}

// ---------------- launch ------------------------------------------------------
extern "C" void kernel_launch(void* const* d_in, const int* in_sizes, int n_in,
                              void* d_out, int out_size) {
    const float* y_pred = (const float*)d_in[0];
    const float* y_obs  = (const float*)d_in[1];
    float* out = (float*)d_out;

    k_zero<<<1, 1>>>();
    k_sortdays<<<dim3(SGRID / K1_SER, NY), 512>>>(y_pred, y_obs);
    k_theil<<<SGRID, 192>>>();
    k_final<<<1, 1>>>(out);
}

// round 3
// speedup vs baseline: 1.5653x; 1.5653x over previous
#include <cuda_runtime.h>
#include <math.h>

#define DAYS  365
#define NY    30
#define SGRID 4000
#define TT    (DAYS * NY)
#define NPAIR 435
#define NQ    5
#define K1_SER 16

#define POSINF __int_as_float(0x7f800000)
#define FULLM  0xffffffffu

// ---------------- intermediate storage (no allocations allowed) -------------
__device__ float  g_pM[SGRID * NY];
__device__ float  g_tM[SGRID * NY];
__device__ float  g_pQ[SGRID * NQ * NY];
__device__ float  g_tQ[SGRID * NQ * NY];
__device__ double g_sse;
__device__ double g_trend;

// ---------------- warp bitonic sort of 512, LANE-MAJOR layout ---------------
// element index g = (lane<<4) | r. Ascending.
// 15 cross-lane stages (240 SHFLs) + 30 reg-reg stages.
// ALL loops have fixed compile-time bounds (guarded by if(j<m)) so every v[r]
// index is a literal -> v stays in registers (the R2 regression was v spilling
// to local memory when the inner loop had outer-var-dependent bounds).
__device__ __forceinline__ void bsort512(float v[16], int lane) {
#pragma unroll
    for (int m = 2; m <= 512; m <<= 1) {
        // cross-lane phases: strides 256..16
#pragma unroll
        for (int j = 256; j >= 16; j >>= 1) {
            if (j < m) {
                int  jl      = j >> 4;
                bool keepmin = (((lane & (m >> 4)) == 0) == ((lane & jl) == 0));
#pragma unroll
                for (int r = 0; r < 16; r++) {
                    float o = __shfl_xor_sync(FULLM, v[r], jl);
                    v[r] = keepmin ? fminf(v[r], o) : fmaxf(v[r], o);
                }
            }
        }
        // register-register phases: strides 8..1
#pragma unroll
        for (int j = 8; j >= 1; j >>= 1) {
            if (j < m) {
#pragma unroll
                for (int r = 0; r < 16; r++) {
                    if ((r & j) == 0) {
                        int  r2 = r | j;
                        bool up = (m >= 16) ? ((lane & (m >> 4)) == 0)
                                            : ((r & m) == 0);
                        float a = v[r], b = v[r2];
                        float lo = fminf(a, b), hi = fmaxf(a, b);
                        v[r]  = up ? lo : hi;
                        v[r2] = up ? hi : lo;
                    }
                }
            }
        }
    }
}

// ---------------- kernel 0: zero accumulators --------------------------------
__global__ void k_zero() {
    g_sse = 0.0;
    g_trend = 0.0;
}

// ---------------- kernel 1: transpose + SSE + per-(series,year) sort ---------
// grid (SGRID/K1_SER, NY), block 512 (16 warps, 1 warp per series)
__global__ __launch_bounds__(512) void k_sortdays(const float* __restrict__ pred,
                                                  const float* __restrict__ obs) {
    __shared__ float shP[K1_SER][DAYS];
    __shared__ float shT[K1_SER][DAYS];
    __shared__ float warpsum[16];

    int y      = blockIdx.y;
    int s_base = blockIdx.x * K1_SER;
    int tid    = threadIdx.x;
    int w      = tid >> 5;
    int lane   = tid & 31;

    const float* pbase = pred + y * DAYS * SGRID + s_base;
    const float* tbase = obs  + y * DAYS * SGRID + s_base;

    // coalesced load + transpose + fused SSE
    float sse = 0.0f;
    for (int idx = tid; idx < DAYS * K1_SER; idx += 512) {
        int d  = idx >> 4;
        int sl = idx & 15;
        float a = pbase[d * SGRID + sl];
        float b = tbase[d * SGRID + sl];
        shP[sl][d] = a;
        shT[sl][d] = b;
        float df = a - b;
        sse += df * df;
    }
#pragma unroll
    for (int o = 16; o > 0; o >>= 1) sse += __shfl_down_sync(FULLM, sse, o);
    if (lane == 0) warpsum[w] = sse;
    __syncthreads();
    if (tid == 0) {
        float tot = 0.0f;
#pragma unroll
        for (int i = 0; i < 16; i++) tot += warpsum[i];
        atomicAdd(&g_sse, (double)tot);
    }

    int s = s_base + w;

#pragma unroll 1
    for (int pass = 0; pass < 2; pass++) {
        float (*sh)[DAYS] = pass ? shT : shP;
        float* outM = pass ? g_tM : g_pM;
        float* outQ = pass ? g_tQ : g_pQ;

        // Conflict-free smem read; value->slot assignment is arbitrary since
        // the sort result is a permutation-invariant function of the set.
        float v[16];
        float msum = 0.0f;
#pragma unroll
        for (int r = 0; r < 16; r++) {
            int g = (r << 5) | lane;
            if (g < DAYS) { v[r] = sh[w][g]; msum += v[r]; }
            else          { v[r] = POSINF; }
        }
        // yearly mean
#pragma unroll
        for (int o = 16; o > 0; o >>= 1) msum += __shfl_down_sync(FULLM, msum, o);
        if (lane == 0) outM[s * NY + y] = msum / (float)DAYS;

        bsort512(v, lane);

        // order statistics (lane-major): rank g -> lane g>>4, reg g&15
        if (lane == 22) {
            outQ[(s * NQ + 0) * NY + y] = v[12];  // g=364
            outQ[(s * NQ + 1) * NY + y] = v[5];   // g=357
        }
        if (lane == 11) outQ[(s * NQ + 2) * NY + y] = v[6];   // g=182
        if (lane == 6)  outQ[(s * NQ + 3) * NY + y] = v[13];  // g=109
        if (lane == 0)  outQ[(s * NQ + 4) * NY + y] = v[7];   // g=7
    }
}

// ---------------- kernel 2: Theil-Sen medians + trend terms ------------------
// grid SGRID, block 192 (6 warps: warp0 = mean, warps 1..5 = quantiles)
__global__ __launch_bounds__(192) void k_theil() {
    __shared__ float xs[6][2][NY];

    int s    = blockIdx.x;
    int w    = threadIdx.x >> 5;
    int lane = threadIdx.x & 31;

    const float* xp;
    const float* xt;
    if (w == 0) { xp = g_pM + s * NY;                  xt = g_tM + s * NY; }
    else        { xp = g_pQ + (s * NQ + (w - 1)) * NY; xt = g_tQ + (s * NQ + (w - 1)) * NY; }
    if (lane < NY) {
        xs[w][0][lane] = xp[lane];
        xs[w][1][lane] = xt[lane];
    }
    __syncwarp();

    float med[2];
#pragma unroll 1
    for (int pass = 0; pass < 2; pass++) {
        float v[16];
#pragma unroll
        for (int r = 0; r < 16; r++) {
            int p = (r << 5) | lane;   // arbitrary pair->slot map (median is set-invariant)
            if (p < NPAIR) {
                int i = 0, rem = p, cnt = NY - 1;
                while (rem >= cnt) { rem -= cnt; i++; cnt--; }
                int j = i + 1 + rem;
                v[r] = (xs[w][pass][j] - xs[w][pass][i]) / (float)(j - i);
            } else {
                v[r] = POSINF;
            }
        }
        bsort512(v, lane);
        // median of 435 = sorted element 217 -> lane 13, reg 9
        med[pass] = __shfl_sync(FULLM, v[9], 13);
    }

    if (lane == 0) {
        float sp = med[0], st = med[1];
        double term;
        if (w == 0) { float d = st - sp;   term = (double)d * (double)d; }
        else        { float q = st / (-sp); term = (double)q * (double)q; }
        atomicAdd(&g_trend, term);
    }
}

// ---------------- kernel 3: finalize -----------------------------------------
__global__ void k_final(float* out) {
    double mse = g_sse / ((double)TT * (double)SGRID);
    out[0] = (float)(sqrt(mse) + g_trend / (double)SGRID);
}

// ---------------- launch ------------------------------------------------------
extern "C" void kernel_launch(void* const* d_in, const int* in_sizes, int n_in,
                              void* d_out, int out_size) {
    const float* y_pred = (const float*)d_in[0];
    const float* y_obs  = (const float*)d_in[1];
    float* out = (float*)d_out;

    k_zero<<<1, 1>>>();
    k_sortdays<<<dim3(SGRID / K1_SER, NY), 512>>>(y_pred, y_obs);
    k_theil<<<SGRID, 192>>>();
    k_final<<<1, 1>>>(out);
}

// round 5
// speedup vs baseline: 1.9653x; 1.2556x over previous
#include <cuda_runtime.h>
#include <math.h>

#define DAYS  365
#define NY    30
#define SGRID 4000
#define TT    (DAYS * NY)
#define NPAIR 435
#define NQ    5
#define K1_SER 16

#define POSINF __int_as_float(0x7f800000)
#define FULLM  0xffffffffu

// ---------------- intermediate storage (no allocations allowed) -------------
__device__ float  g_pM[SGRID * NY];
__device__ float  g_tM[SGRID * NY];
__device__ float  g_pQ[SGRID * NQ * NY];
__device__ float  g_tQ[SGRID * NQ * NY];
__device__ double g_sse;
__device__ double g_trend;

// in-lane comparator, compile-time direction: a <- min, b <- max (2 FMNMX)
__device__ __forceinline__ void cswap(float& a, float& b) {
    float lo = fminf(a, b);
    float hi = fmaxf(a, b);
    a = lo; b = hi;
}

// ---------------- normalized (flip) bitonic sort of 512, lane-major ----------
// element position g = lane*16 + r. Ascending.
// Every in-lane comparator direction is compile-time (min -> lower reg).
// Cross-lane stages: 15 total, one predicated FMNMX + one SHFL per reg.
// All loops fixed-bound + guarded so v[] indices are literals (stays in regs).
__device__ __forceinline__ void bsort512(float v[16], int lane) {
    // ---- in-lane levels k = 2..16 (r bits only) ----
#pragma unroll
    for (int k = 2; k <= 16; k <<= 1) {
        // flip substage: pairs (r, r^(k-1)) for (r mod k) < k/2
#pragma unroll
        for (int r = 0; r < 16; r++)
            if ((r & (k - 1)) < (k >> 1)) cswap(v[r], v[r ^ (k - 1)]);
        // plain substages j = k/4 .. 1
#pragma unroll
        for (int j = 8; j >= 1; j >>= 1)
            if (j <= (k >> 2)) {
#pragma unroll
                for (int r = 0; r < 16; r++)
                    if ((r & j) == 0) cswap(v[r], v[r | j]);
            }
    }
    // ---- cross-lane levels k = 32..512 ----
#pragma unroll
    for (int k = 32; k <= 512; k <<= 1) {
        // flip substage: partner lane = lane ^ ((k-1)>>4), partner reg = 15-r.
        // This lane keeps min iff its top differing lane bit (k>>5) is 0.
        {
            int  lm      = (k - 1) >> 4;
            bool keepmin = ((lane & (k >> 5)) == 0);
#pragma unroll
            for (int r = 0; r < 8; r++) {
                float a = __shfl_xor_sync(FULLM, v[15 - r], lm); // partner's v[15-r]
                float b = __shfl_xor_sync(FULLM, v[r], lm);      // partner's v[r]
                v[r]      = keepmin ? fminf(v[r], a)      : fmaxf(v[r], a);
                v[15 - r] = keepmin ? fminf(v[15 - r], b) : fmaxf(v[15 - r], b);
            }
        }
        // plain cross-lane substages j = k/4 .. 16 (same reg across lanes)
#pragma unroll
        for (int j = 128; j >= 16; j >>= 1)
            if (j <= (k >> 2)) {
                int  lm      = j >> 4;
                bool keepmin = ((lane & lm) == 0);
#pragma unroll
                for (int r = 0; r < 16; r++) {
                    float o = __shfl_xor_sync(FULLM, v[r], lm);
                    v[r] = keepmin ? fminf(v[r], o) : fmaxf(v[r], o);
                }
            }
        // plain in-lane substages j = 8..1 (compile-time direction)
#pragma unroll
        for (int j = 8; j >= 1; j >>= 1) {
#pragma unroll
            for (int r = 0; r < 16; r++)
                if ((r & j) == 0) cswap(v[r], v[r | j]);
        }
    }
}

// ---------------- kernel 0: zero accumulators --------------------------------
__global__ void k_zero() {
    g_sse = 0.0;
    g_trend = 0.0;
}

// ---------------- kernel 1: transpose + SSE + per-(series,year) sort ---------
// grid (SGRID/K1_SER, NY), block 512 (16 warps, 1 warp per series)
__global__ __launch_bounds__(512) void k_sortdays(const float* __restrict__ pred,
                                                  const float* __restrict__ obs) {
    __shared__ float shP[K1_SER][DAYS];
    __shared__ float shT[K1_SER][DAYS];
    __shared__ float warpsum[16];

    int y      = blockIdx.y;
    int s_base = blockIdx.x * K1_SER;
    int tid    = threadIdx.x;
    int w      = tid >> 5;
    int lane   = tid & 31;

    const float* pbase = pred + y * DAYS * SGRID + s_base;
    const float* tbase = obs  + y * DAYS * SGRID + s_base;

    // coalesced load + transpose + fused SSE
    float sse = 0.0f;
    for (int idx = tid; idx < DAYS * K1_SER; idx += 512) {
        int d  = idx >> 4;
        int sl = idx & 15;
        float a = pbase[d * SGRID + sl];
        float b = tbase[d * SGRID + sl];
        shP[sl][d] = a;
        shT[sl][d] = b;
        float df = a - b;
        sse += df * df;
    }
#pragma unroll
    for (int o = 16; o > 0; o >>= 1) sse += __shfl_down_sync(FULLM, sse, o);
    if (lane == 0) warpsum[w] = sse;
    __syncthreads();
    if (tid == 0) {
        float tot = 0.0f;
#pragma unroll
        for (int i = 0; i < 16; i++) tot += warpsum[i];
        atomicAdd(&g_sse, (double)tot);
    }

    int s = s_base + w;

#pragma unroll 1
    for (int pass = 0; pass < 2; pass++) {
        float (*sh)[DAYS] = pass ? shT : shP;
        float* outM = pass ? g_tM : g_pM;
        float* outQ = pass ? g_tQ : g_pQ;

        // Conflict-free smem read; value->slot assignment is an arbitrary
        // permutation (sorted output is set-invariant).
        float v[16];
        float msum = 0.0f;
#pragma unroll
        for (int r = 0; r < 16; r++) {
            int g = (r << 5) | lane;
            if (g < DAYS) { v[r] = sh[w][g]; msum += v[r]; }
            else          { v[r] = POSINF; }
        }
        // yearly mean
#pragma unroll
        for (int o = 16; o > 0; o >>= 1) msum += __shfl_down_sync(FULLM, msum, o);
        if (lane == 0) outM[s * NY + y] = msum / (float)DAYS;

        bsort512(v, lane);

        // order statistics (lane-major): rank g -> lane = g>>4, reg = g&15
        if (lane == 22) {
            outQ[(s * NQ + 0) * NY + y] = v[12];  // g=364
            outQ[(s * NQ + 1) * NY + y] = v[5];   // g=357
        }
        if (lane == 11) outQ[(s * NQ + 2) * NY + y] = v[6];   // g=182
        if (lane == 6)  outQ[(s * NQ + 3) * NY + y] = v[13];  // g=109
        if (lane == 0)  outQ[(s * NQ + 4) * NY + y] = v[7];   // g=7
    }
}

// ---------------- kernel 2: Theil-Sen medians + trend terms ------------------
// grid SGRID, block 192 (6 warps: warp0 = mean, warps 1..5 = quantiles)
__global__ __launch_bounds__(192) void k_theil() {
    __shared__ float xs[6][2][NY];

    int s    = blockIdx.x;
    int w    = threadIdx.x >> 5;
    int lane = threadIdx.x & 31;

    const float* xp;
    const float* xt;
    if (w == 0) { xp = g_pM + s * NY;                  xt = g_tM + s * NY; }
    else        { xp = g_pQ + (s * NQ + (w - 1)) * NY; xt = g_tQ + (s * NQ + (w - 1)) * NY; }
    if (lane < NY) {
        xs[w][0][lane] = xp[lane];
        xs[w][1][lane] = xt[lane];
    }
    __syncwarp();

    float med[2];
#pragma unroll 1
    for (int pass = 0; pass < 2; pass++) {
        float v[16];
#pragma unroll
        for (int r = 0; r < 16; r++) {
            int p = (r << 5) | lane;   // arbitrary pair->slot map (median is set-invariant)
            if (p < NPAIR) {
                int i = 0, rem = p, cnt = NY - 1;
                while (rem >= cnt) { rem -= cnt; i++; cnt--; }
                int j = i + 1 + rem;
                v[r] = (xs[w][pass][j] - xs[w][pass][i]) / (float)(j - i);
            } else {
                v[r] = POSINF;
            }
        }
        bsort512(v, lane);
        // median of 435 = sorted element 217 -> lane 13, reg 9
        med[pass] = __shfl_sync(FULLM, v[9], 13);
    }

    if (lane == 0) {
        float sp = med[0], st = med[1];
        double term;
        if (w == 0) { float d = st - sp;   term = (double)d * (double)d; }
        else        { float q = st / (-sp); term = (double)q * (double)q; }
        atomicAdd(&g_trend, term);
    }
}

// ---------------- kernel 3: finalize -----------------------------------------
__global__ void k_final(float* out) {
    double mse = g_sse / ((double)TT * (double)SGRID);
    out[0] = (float)(sqrt(mse) + g_trend / (double)SGRID);
}

// ---------------- launch ------------------------------------------------------
extern "C" void kernel_launch(void* const* d_in, const int* in_sizes, int n_in,
                              void* d_out, int out_size) {
    const float* y_pred = (const float*)d_in[0];
    const float* y_obs  = (const float*)d_in[1];
    float* out = (float*)d_out;

    k_zero<<<1, 1>>>();
    k_sortdays<<<dim3(SGRID / K1_SER, NY), 512>>>(y_pred, y_obs);
    k_theil<<<SGRID, 192>>>();
    k_final<<<1, 1>>>(out);
}